// round 13
// baseline (speedup 1.0000x reference)
#include <cuda_runtime.h>
#include <cstdint>

// Per-batch exact integer accumulators: [n] = {sum_y(=Σ R*i), sum_x(=Σ R*j), count}
__device__ int g_acc[64][3];
__device__ float g_ts[64][2];   // target center sums, written by block 0 each run
__device__ int g_done;          // arrival counter, reset by the final block

// ---------------- PTX helpers ----------------
__device__ __forceinline__ uint32_t smem_u32(const void* p) {
    uint32_t a;
    asm("{ .reg .u64 t; cvta.to.shared.u64 t, %1; cvt.u32.u64 %0, t; }" : "=r"(a) : "l"(p));
    return a;
}
__device__ __forceinline__ void mbar_init(uint32_t mbar, uint32_t count) {
    asm volatile("mbarrier.init.shared.b64 [%0], %1;" :: "r"(mbar), "r"(count) : "memory");
}
__device__ __forceinline__ void fence_proxy_async_shared() {
    asm volatile("fence.proxy.async.shared::cta;" ::: "memory");
}
__device__ __forceinline__ void mbar_expect_tx(uint32_t mbar, uint32_t bytes) {
    asm volatile("mbarrier.arrive.expect_tx.shared.b64 _, [%0], %1;" :: "r"(mbar), "r"(bytes) : "memory");
}
__device__ __forceinline__ void bulk_g2s(uint32_t dst, const void* src, uint32_t bytes, uint32_t mbar) {
    asm volatile("cp.async.bulk.shared::cta.global.mbarrier::complete_tx::bytes [%0], [%1], %2, [%3];"
        :: "r"(dst), "l"(src), "r"(bytes), "r"(mbar) : "memory");
}
__device__ __forceinline__ void mbar_wait(uint32_t mbar, uint32_t parity) {
    asm volatile(
        "{\n\t"
        ".reg .pred P;\n\t"
        "WAIT_%=:\n\t"
        "mbarrier.try_wait.parity.acquire.cta.shared::cta.b64 P, [%0], %1, 0x989680;\n\t"
        "@P bra.uni DONE_%=;\n\t"
        "bra.uni WAIT_%=;\n\t"
        "DONE_%=:\n\t"
        "}" :: "r"(mbar), "r"(parity) : "memory");
}

__device__ __forceinline__ void ld8(const float* p, float o[8]) {
    float4 d0 = *(const float4*)p;
    float4 d1 = *(const float4*)(p + 4);
    o[0]=d0.x; o[1]=d0.y; o[2]=d0.z; o[3]=d0.w;
    o[4]=d1.x; o[5]=d1.y; o[6]=d1.z; o[7]=d1.w;
}

// ---------------------------------------------------------------------------
// Variant A (p1, W=256): each lane owns 8 cols (2 float4) of a 256-col row.
// Warp w computes 4 output rows. All data from SMEM band (pitch 256 floats).
// ---------------------------------------------------------------------------
__device__ __forceinline__ void compute_p1_warp(
    const float* __restrict__ band, int srmax, int load_start, int w, int lane,
    int& sy, int& sx, int& sc)
{
    const int c0 = 8 * lane;
    const int sr_first = 1 + 4 * w;
    const float* bp = band + c0;

    float a[8], b[8], c[8];
    ld8(bp + min(sr_first - 1, srmax) * 256, a);
    ld8(bp + min(sr_first,     srmax) * 256, b);

#pragma unroll
    for (int k = 0; k < 4; ++k) {
        const int sr = sr_first + k;
        ld8(bp + min(sr + 1, srmax) * 256, c);
        const int out_row = load_start + sr;

        float vb[8], m3v[8];
#pragma unroll
        for (int j = 0; j < 8; ++j) {
            const float v = fmaxf(a[j], c[j]);
            vb[j]  = v;
            m3v[j] = fmaxf(v, b[j]);
        }
        const float mL = __shfl_up_sync(0xFFFFFFFFu, m3v[7], 1);
        const float mR = __shfl_down_sync(0xFFFFFFFFu, m3v[0], 1);

        bool pk[8];
#pragma unroll
        for (int j = 0; j < 8; ++j) {
            const float l = (j == 0) ? mL : m3v[j - 1];
            const float r = (j == 7) ? mR : m3v[j + 1];
            pk[j] = (b[j] > vb[j]) & (b[j] > l) & (b[j] > r);
        }
        if (lane == 0)  pk[0] = false;   // col 0 is image edge
        if (lane == 31) pk[7] = false;   // col 255 is image edge

        if (out_row <= 254) {
            int npk = 0, joff = 0;
#pragma unroll
            for (int j = 0; j < 8; ++j) { npk += (int)pk[j]; joff += j * (int)pk[j]; }
            sc += npk;
            sy += out_row * npk;
            sx += c0 * npk + joff;
        }
#pragma unroll
        for (int j = 0; j < 8; ++j) { a[j] = b[j]; b[j] = c[j]; }
    }
}

// ---------------------------------------------------------------------------
// Variant B (p2/p3): lane owns 4 cols (1 float4); LANE_W lanes cover PW cols.
// Computes nrows rows starting at smem row sr_first (global = row_off + sr).
// ---------------------------------------------------------------------------
template<int PW, int LANE_W>
__device__ __forceinline__ void compute4(
    const float* __restrict__ band, int srmax, int sr_first, int nrows,
    int row_off, int last_out, int lane, int& sy, int& sx, int& sc)
{
    const int li = lane % LANE_W;
    const unsigned mask = (LANE_W == 32) ? 0xFFFFFFFFu : (0xFFFFu << (lane & 16));
    const int c0 = 4 * li;
    const bool m0  = (c0 == 0);
    const bool m3e = (c0 + 3 == PW - 1);
    const float* bp = band + c0;

    float4 A = *(const float4*)(bp + min(sr_first - 1, srmax) * PW);
    float4 B = *(const float4*)(bp + min(sr_first,     srmax) * PW);

    for (int k = 0; k < nrows; ++k) {
        const int sr = sr_first + k;
        const float4 C = *(const float4*)(bp + min(sr + 1, srmax) * PW);
        const int out_row = row_off + sr;

        const float vACx = fmaxf(A.x, C.x), vACy = fmaxf(A.y, C.y);
        const float vACz = fmaxf(A.z, C.z), vACw = fmaxf(A.w, C.w);
        const float m3x = fmaxf(vACx, B.x), m3y = fmaxf(vACy, B.y);
        const float m3z = fmaxf(vACz, B.z), m3w = fmaxf(vACw, B.w);

        const float mL = __shfl_up_sync(mask, m3w, 1, LANE_W);
        const float mR = __shfl_down_sync(mask, m3x, 1, LANE_W);

        const bool pk0 = !m0  && (B.x > vACx) && (B.x > mL)  && (B.x > m3y);
        const bool pk1 =         (B.y > vACy) && (B.y > m3x) && (B.y > m3z);
        const bool pk2 =         (B.z > vACz) && (B.z > m3y) && (B.z > m3w);
        const bool pk3 = !m3e && (B.w > vACw) && (B.w > m3z) && (B.w > mR);

        if (out_row <= last_out) {
            const int npk = (int)pk0 + (int)pk1 + (int)pk2 + (int)pk3;
            sc += npk;
            sy += out_row * npk;
            sx += c0 * npk + (int)pk1 + 2 * (int)pk2 + 3 * (int)pk3;
        }
        A = B; B = C;
    }
}

// ---------------------------------------------------------------------------
// Single fused kernel, TMA-bulk-fed. Grid = 704 blocks x 256 threads:
//   [0,512):   p1: n=b>>3, band=b&7 (34-row bands, 32 output rows)
//   [512,640): p2: t=b-512, n=t>>1, half=t&1 (65-row bands, 63 output rows)
//   [640,704): p3: n=b-640 (whole 64x64 image)
// ---------------------------------------------------------------------------
__global__ void __launch_bounds__(256, 5) offset_loss_kernel(
    const float* __restrict__ p1,
    const float* __restrict__ p2,
    const float* __restrict__ p3,
    const float* __restrict__ target,
    float* __restrict__ out)
{
    __shared__ alignas(128) float band[8704];         // 34 KB max band, TMA-aligned
    __shared__ alignas(8) unsigned long long mbar8;
    __shared__ int s_last;

    const int tid = threadIdx.x;
    const int bid = blockIdx.x;
    const int lane = tid & 31;
    const int w = tid >> 5;

    // ---- decode band, compute source pointer/bytes ----
    const float* src;
    uint32_t bytes;
    int n, level, bsub, load_start, srmax;
    if (bid < 512) {
        level = 0; n = bid >> 3; bsub = bid & 7;
        load_start = 32 * bsub;
        const int rows = (bsub < 7) ? 34 : 32;
        srmax = rows - 1;
        src = p1 + ((size_t)n * 3 + 2) * 65536 + (size_t)load_start * 256;
        bytes = rows * 256 * 4;
    } else if (bid < 640) {
        const int t = bid - 512;
        level = 1; n = t >> 1; bsub = t & 1;
        load_start = 63 * bsub;                       // 0 or 63
        srmax = 64;                                   // 65 rows
        src = p2 + ((size_t)n * 3 + 2) * 16384 + (size_t)load_start * 128;
        bytes = 65 * 128 * 4;
    } else {
        level = 2; n = bid - 640; bsub = 0;
        load_start = 0;
        srmax = 63;
        src = p3 + ((size_t)n * 3 + 2) * 4096;
        bytes = 64 * 64 * 4;
    }

    // ---- issue bulk copy ----
    const uint32_t s_band = smem_u32(band);
    const uint32_t s_mbar = smem_u32(&mbar8);
    if (tid == 0) {
        mbar_init(s_mbar, 1);
        fence_proxy_async_shared();   // order init before async-proxy TMA access
    }
    __syncthreads();
    if (tid == 0) {
        mbar_expect_tx(s_mbar, bytes);
        bulk_g2s(s_band, src, bytes, s_mbar);
    }

    // ---- block 0: target center sums while its copy is in flight ----
    if (bid == 0) {
        const int tn = tid >> 2;
        const int q = tid & 3;
        const float* tb = target + (size_t)tn * 32 * 5 + q * 8 * 5;
        float t0 = 0.f, t1 = 0.f;
#pragma unroll
        for (int k = 0; k < 8; k++) {
            const float* bx = tb + k * 5;
            t0 += (bx[0] + bx[2]) * 0.5f;
            t1 += (bx[1] + bx[3]) * 0.5f;
        }
        t0 += __shfl_xor_sync(0xFFFFFFFFu, t0, 1);
        t1 += __shfl_xor_sync(0xFFFFFFFFu, t1, 1);
        t0 += __shfl_xor_sync(0xFFFFFFFFu, t0, 2);
        t1 += __shfl_xor_sync(0xFFFFFFFFu, t1, 2);
        if (q == 0) {
            g_ts[tn][0] = t0;
            g_ts[tn][1] = t1;
            __threadfence();   // order before this block's g_done arrival
        }
    }

    // ---- wait for data, compute ----
    mbar_wait(s_mbar, 0);

    int sy = 0, sx = 0, sc = 0, R;
    if (level == 0) {
        R = 4;
        compute_p1_warp(band, srmax, load_start, w, lane, sy, sx, sc);
    } else if (level == 1) {
        R = 8;
        // warp w: 8 rows starting at smem row 1+8w; band half 0 outputs rows 1..63,
        // half 1 outputs rows 64..126 (global = load_start + sr).
        const int last_out = (bsub == 0) ? 63 : 126;
        compute4<128, 32>(band, srmax, 1 + 8 * w, 8, load_start, last_out,
                          lane, sy, sx, sc);
    } else {
        R = 16;
        // 16 groups of 16 lanes; group g2 computes 4 rows starting at 1+4*g2.
        const int g2 = w * 2 + (lane >> 4);
        compute4<64, 16>(band, srmax, 1 + 4 * g2, 4, 0, 62, lane, sy, sx, sc);
    }

    // per-warp exact integer reduction + atomics
    sy = __reduce_add_sync(0xFFFFFFFFu, sy);
    sx = __reduce_add_sync(0xFFFFFFFFu, sx);
    sc = __reduce_add_sync(0xFFFFFFFFu, sc);
    if (lane == 0 && sc) {
        atomicAdd(&g_acc[n][0], R * sy);
        atomicAdd(&g_acc[n][1], R * sx);
        atomicAdd(&g_acc[n][2], sc);
    }

    // ---- arrival: last block finalizes ----
    __syncthreads();
    if (tid == 0) {
        __threadfence();
        const int ticket = atomicAdd(&g_done, 1);
        s_last = (ticket == gridDim.x - 1) ? 1 : 0;
    }
    __syncthreads();
    if (!s_last) return;

    __threadfence();

    float off0 = 0.f, off1 = 0.f, cs0 = 0.f, cs1 = 0.f, ts0 = 0.f, ts1 = 0.f;
    int cnt = 0;
    if (tid < 64) {
        volatile int* acc = &g_acc[tid][0];
        const float c0 = (float)acc[0];
        const float c1 = (float)acc[1];
        cnt = acc[2];
        volatile float* ts = &g_ts[tid][0];
        ts0 = ts[0]; ts1 = ts[1];

        const float d0 = fabsf(c0 - ts0);
        const float d1 = fabsf(c1 - ts1);
        off0 = (d0 < 1.f) ? 0.5f * d0 * d0 : d0 - 0.5f;
        off1 = (d1 < 1.f) ? 0.5f * d1 * d1 : d1 - 0.5f;
        cs0 = c0; cs1 = c1;

        acc[0] = 0; acc[1] = 0; acc[2] = 0;   // reset for next replay
    }

#pragma unroll
    for (int d = 16; d > 0; d >>= 1) {
        off0 += __shfl_down_sync(0xFFFFFFFFu, off0, d);
        off1 += __shfl_down_sync(0xFFFFFFFFu, off1, d);
        cs0  += __shfl_down_sync(0xFFFFFFFFu, cs0, d);
        cs1  += __shfl_down_sync(0xFFFFFFFFu, cs1, d);
        ts0  += __shfl_down_sync(0xFFFFFFFFu, ts0, d);
        ts1  += __shfl_down_sync(0xFFFFFFFFu, ts1, d);
        cnt  += __shfl_down_sync(0xFFFFFFFFu, cnt, d);
    }
    __shared__ float sh[2][6];
    __shared__ int shc[2];
    if (tid < 64 && (tid & 31) == 0) {
        const int wg = tid >> 5;
        sh[wg][0] = off0; sh[wg][1] = off1; sh[wg][2] = cs0;
        sh[wg][3] = cs1;  sh[wg][4] = ts0;  sh[wg][5] = ts1;
        shc[wg] = cnt;
    }
    __syncthreads();
    if (tid == 0) {
        const float OFF0 = sh[0][0] + sh[1][0];
        const float OFF1 = sh[0][1] + sh[1][1];
        const float CS0  = sh[0][2] + sh[1][2];
        const float CS1  = sh[0][3] + sh[1][3];
        const float TS0  = sh[0][4] + sh[1][4];
        const float TS1  = sh[0][5] + sh[1][5];
        const float PSUM = (float)(shc[0] + shc[1]);
        out[0] = (OFF0 / fabsf(OFF0) * (CS0 - TS0) +
                  OFF1 / fabsf(OFF1) * (CS1 - TS1)) / PSUM;
        g_done = 0;   // reset arrival counter for next replay
    }
}

extern "C" void kernel_launch(void* const* d_in, const int* in_sizes, int n_in,
                              void* d_out, int out_size) {
    const float *p1 = nullptr, *p2 = nullptr, *p3 = nullptr, *tg = nullptr;
    for (int k = 0; k < n_in; k++) {
        switch (in_sizes[k]) {
            case 64 * 3 * 256 * 256: p1 = (const float*)d_in[k]; break;
            case 64 * 3 * 128 * 128: p2 = (const float*)d_in[k]; break;
            case 64 * 3 * 64 * 64:   p3 = (const float*)d_in[k]; break;
            case 64 * 32 * 5:        tg = (const float*)d_in[k]; break;
            default: break;
        }
    }

    // 704 blocks x 256 threads; single wave (5 blocks/SM); single launch.
    offset_loss_kernel<<<704, 256>>>(p1, p2, p3, tg, (float*)d_out);
}

// round 17
// speedup vs baseline: 1.1092x; 1.1092x over previous
#include <cuda_runtime.h>

// Per-batch exact integer accumulators: [n] = {sum_y(=Σ R*i), sum_x(=Σ R*j), count}
__device__ int g_acc[64][3];
__device__ float g_ts[64][2];   // target center sums, written by block 0 each run
__device__ int g_done;          // arrival counter, reset by the final block
__device__ int g_work;          // work-queue counter, reset by the final block

#define NUM_UNITS 5376

// ---------------------------------------------------------------------------
// Batched-load 8-row strip (R8-proven): load ALL 10 rows (8 compute + 2 halo)
// into registers first (front-batched LDG.128 -> MLP~10), then compute.
// Peak(i,j) <=> B[j] > max(vAC[j], vm3[j-1], vm3[j+1]).
// ---------------------------------------------------------------------------
template<int W, int R, int LANE_W>
__device__ __forceinline__ void process_strip8(
    const float* __restrict__ img,   // channel-2 base for this batch
    int n, int i_begin, int i_end, int col_base)
{
    constexpr bool HALO = (4 * LANE_W < W);   // only p1 (two 128-col strips)
    const int lane = threadIdx.x & 31;
    const int li   = lane % LANE_W;
    const unsigned shfl_mask = (LANE_W == 32) ? 0xFFFFFFFFu
                                              : (0xFFFFu << (lane & 16));
    const int col0 = col_base + 4 * li;
    const bool hl = HALO && (col_base > 0) && (li == 0);
    const bool hr = HALO && (col_base + 4 * LANE_W < W) && (li == LANE_W - 1);
    const bool m0 = (col0 == 0);          // element 0 on image edge
    const bool m3 = (col0 + 3 == W - 1);  // element 3 on image edge
    const float* p = img + col0;

    // ---- load phase: 10 rows, clamped (duplicates hit L1) ----
    float4 rv[10];
#pragma unroll
    for (int k = 0; k < 10; ++k) {
        int r = i_begin - 1 + k; if (r > i_end + 1) r = i_end + 1;
        rv[k] = __ldg((const float4*)(p + (size_t)r * W));
    }
    float hLv[10], hRv[10];
    if (HALO) {
#pragma unroll
        for (int k = 0; k < 10; ++k) {
            int r = i_begin - 1 + k; if (r > i_end + 1) r = i_end + 1;
            hLv[k] = hl ? __ldg(p + (size_t)r * W - 1) : 0.f;
            hRv[k] = hr ? __ldg(p + (size_t)r * W + 4) : 0.f;
        }
    }

    // ---- compute phase ----
    int sy = 0, sx = 0, sc = 0;
#pragma unroll
    for (int k = 1; k <= 8; ++k) {
        const int i = i_begin + k - 1;
        const float4 A = rv[k - 1], B = rv[k], C = rv[k + 1];

        const float vACx = fmaxf(A.x, C.x), vACy = fmaxf(A.y, C.y);
        const float vACz = fmaxf(A.z, C.z), vACw = fmaxf(A.w, C.w);
        const float m3x = fmaxf(vACx, B.x), m3y = fmaxf(vACy, B.y);
        const float m3z = fmaxf(vACz, B.z), m3w = fmaxf(vACw, B.w);

        float mL = __shfl_up_sync(shfl_mask, m3w, 1, LANE_W);
        float mR = __shfl_down_sync(shfl_mask, m3x, 1, LANE_W);
        if (HALO) {
            if (hl) mL = fmaxf(fmaxf(hLv[k - 1], hLv[k]), hLv[k + 1]);
            if (hr) mR = fmaxf(fmaxf(hRv[k - 1], hRv[k]), hRv[k + 1]);
        }

        const bool pk0 = !m0 && (B.x > vACx) && (B.x > mL)  && (B.x > m3y);
        const bool pk1 =        (B.y > vACy) && (B.y > m3x) && (B.y > m3z);
        const bool pk2 =        (B.z > vACz) && (B.z > m3y) && (B.z > m3w);
        const bool pk3 = !m3 && (B.w > vACw) && (B.w > m3z) && (B.w > mR);

        if (i <= i_end) {
            const int npk = (int)pk0 + (int)pk1 + (int)pk2 + (int)pk3;
            sc += npk;
            sy += i * npk;
            sx += col0 * npk + (int)pk1 + 2 * (int)pk2 + 3 * (int)pk3;
        }
    }

    // warp-wide reduction (both LANE_W=16 groups target the same batch n)
    sy = __reduce_add_sync(0xFFFFFFFFu, sy);
    sx = __reduce_add_sync(0xFFFFFFFFu, sx);
    sc = __reduce_add_sync(0xFFFFFFFFu, sc);
    if (lane == 0 && sc) {
        atomicAdd(&g_acc[n][0], R * sy);
        atomicAdd(&g_acc[n][1], R * sx);
        atomicAdd(&g_acc[n][2], sc);
    }
}

// Decode + process one 8-row strip unit:
//   [0,4096):    p1: n=id>>6; sub=id&63: cs=sub&1, rs=sub>>1 (0..31)
//   [4096,5120): p2: t=id-4096: n=t>>4, rs=t&15
//   [5120,5376): p3: t=id-5120: n=t>>2, rs=t&3; two 16-lane groups,
//                    each an 8-row segment (seg = rs*2 + group)
__device__ __forceinline__ void process_unit(
    int id, const float* __restrict__ p1, const float* __restrict__ p2,
    const float* __restrict__ p3)
{
    if (id < 4096) {
        const int n = id >> 6;
        const int sub = id & 63;
        const int cs = sub & 1;
        const int rs = sub >> 1;
        const int i_begin = 1 + rs * 8;
        const int i_end = min(i_begin + 7, 254);
        const float* img = p1 + ((size_t)n * 3 + 2) * 65536;
        process_strip8<256, 4, 32>(img, n, i_begin, i_end, cs * 128);
    } else if (id < 5120) {
        const int t = id - 4096;
        const int n = t >> 4;
        const int rs = t & 15;
        const int i_begin = 1 + rs * 8;
        const int i_end = min(i_begin + 7, 126);
        const float* img = p2 + ((size_t)n * 3 + 2) * 16384;
        process_strip8<128, 8, 32>(img, n, i_begin, i_end, 0);
    } else {
        const int t = id - 5120;
        const int n = t >> 2;
        const int rs = t & 3;
        const int group = (threadIdx.x & 31) >> 4;
        const int seg = rs * 2 + group;
        const int i_begin = 1 + seg * 8;
        const int i_end = min(i_begin + 7, 62);
        const float* img = p3 + ((size_t)n * 3 + 2) * 4096;
        process_strip8<64, 16, 16>(img, n, i_begin, i_end, 0);
    }
}

// ---------------------------------------------------------------------------
// Persistent single-wave kernel: 592 blocks (148 SMs x 4) x 128 threads.
// Warps pull 8-row strip units from a global queue until drained, then the
// last-arriving block computes the final scalar loss.
// ---------------------------------------------------------------------------
__global__ void __launch_bounds__(128, 4) offset_loss_kernel(
    const float* __restrict__ p1,
    const float* __restrict__ p2,
    const float* __restrict__ p3,
    const float* __restrict__ target,
    float* __restrict__ out)
{
    const int tid = threadIdx.x;
    const int lane = tid & 31;

    // Block 0 computes target center sums first (hidden under other blocks' work).
    if (blockIdx.x == 0) {
        const int tn = tid >> 1;       // 0..63
        const int q = tid & 1;         // 16 boxes each
        const float* tb = target + (size_t)tn * 32 * 5 + q * 16 * 5;
        float t0 = 0.f, t1 = 0.f;
#pragma unroll
        for (int k = 0; k < 16; k++) {
            const float* b = tb + k * 5;
            t0 += (b[0] + b[2]) * 0.5f;
            t1 += (b[1] + b[3]) * 0.5f;
        }
        t0 += __shfl_xor_sync(0xFFFFFFFFu, t0, 1);
        t1 += __shfl_xor_sync(0xFFFFFFFFu, t1, 1);
        if (q == 0) {
            g_ts[tn][0] = t0;
            g_ts[tn][1] = t1;
            __threadfence();   // order before this block's g_done arrival
        }
    }

    // ---- persistent work loop: grab units until the queue drains ----
    // Seed each warp with a statically assigned first unit (avoids an initial
    // atomic storm), then switch to dynamic grabbing.
    const int gw = blockIdx.x * 4 + (tid >> 5);     // 0..2367
    int id = gw;
    for (;;) {
        if (id >= NUM_UNITS) break;
        process_unit(id, p1, p2, p3);
        if (lane == 0) id = 2368 + atomicAdd(&g_work, 1);
        id = __shfl_sync(0xFFFFFFFFu, id, 0);
    }

    // ---- arrival: last block finalizes ----
    __shared__ int s_last;
    __syncthreads();
    if (tid == 0) {
        __threadfence();
        const int ticket = atomicAdd(&g_done, 1);
        s_last = (ticket == gridDim.x - 1) ? 1 : 0;
    }
    __syncthreads();
    if (!s_last) return;

    __threadfence();

    float off0 = 0.f, off1 = 0.f, cs0 = 0.f, cs1 = 0.f, ts0 = 0.f, ts1 = 0.f;
    int cnt = 0;
    if (tid < 64) {
        volatile int* acc = &g_acc[tid][0];
        const float c0 = (float)acc[0];   // center_sum[:,0]
        const float c1 = (float)acc[1];   // center_sum[:,1]
        cnt = acc[2];
        volatile float* ts = &g_ts[tid][0];
        ts0 = ts[0]; ts1 = ts[1];

        const float d0 = fabsf(c0 - ts0);
        const float d1 = fabsf(c1 - ts1);
        off0 = (d0 < 1.f) ? 0.5f * d0 * d0 : d0 - 0.5f;
        off1 = (d1 < 1.f) ? 0.5f * d1 * d1 : d1 - 0.5f;
        cs0 = c0; cs1 = c1;

        acc[0] = 0; acc[1] = 0; acc[2] = 0;   // reset for next replay
    }

    // reduce over 64 active threads (2 full warps; warps 2,3 contribute zeros)
#pragma unroll
    for (int d = 16; d > 0; d >>= 1) {
        off0 += __shfl_down_sync(0xFFFFFFFFu, off0, d);
        off1 += __shfl_down_sync(0xFFFFFFFFu, off1, d);
        cs0  += __shfl_down_sync(0xFFFFFFFFu, cs0, d);
        cs1  += __shfl_down_sync(0xFFFFFFFFu, cs1, d);
        ts0  += __shfl_down_sync(0xFFFFFFFFu, ts0, d);
        ts1  += __shfl_down_sync(0xFFFFFFFFu, ts1, d);
        cnt  += __shfl_down_sync(0xFFFFFFFFu, cnt, d);
    }
    __shared__ float sh[2][6];
    __shared__ int shc[2];
    if (tid < 64 && (tid & 31) == 0) {
        const int wg = tid >> 5;
        sh[wg][0] = off0; sh[wg][1] = off1; sh[wg][2] = cs0;
        sh[wg][3] = cs1;  sh[wg][4] = ts0;  sh[wg][5] = ts1;
        shc[wg] = cnt;
    }
    __syncthreads();
    if (tid == 0) {
        const float OFF0 = sh[0][0] + sh[1][0];
        const float OFF1 = sh[0][1] + sh[1][1];
        const float CS0  = sh[0][2] + sh[1][2];
        const float CS1  = sh[0][3] + sh[1][3];
        const float TS0  = sh[0][4] + sh[1][4];
        const float TS1  = sh[0][5] + sh[1][5];
        const float PSUM = (float)(shc[0] + shc[1]);
        out[0] = (OFF0 / fabsf(OFF0) * (CS0 - TS0) +
                  OFF1 / fabsf(OFF1) * (CS1 - TS1)) / PSUM;
        g_work = 0;   // reset queue for next replay
        g_done = 0;   // reset arrival counter for next replay
    }
}

extern "C" void kernel_launch(void* const* d_in, const int* in_sizes, int n_in,
                              void* d_out, int out_size) {
    const float *p1 = nullptr, *p2 = nullptr, *p3 = nullptr, *tg = nullptr;
    for (int k = 0; k < n_in; k++) {
        switch (in_sizes[k]) {
            case 64 * 3 * 256 * 256: p1 = (const float*)d_in[k]; break;
            case 64 * 3 * 128 * 128: p2 = (const float*)d_in[k]; break;
            case 64 * 3 * 64 * 64:   p3 = (const float*)d_in[k]; break;
            case 64 * 32 * 5:        tg = (const float*)d_in[k]; break;
            default: break;
        }
    }

    // 592 blocks = 148 SMs x 4; 128 threads; single wave; persistent work queue.
    offset_loss_kernel<<<592, 128>>>(p1, p2, p3, tg, (float*)d_out);
}